// round 4
// baseline (speedup 1.0000x reference)
#include <cuda_runtime.h>
#include <math.h>

// Problem constants
#define HH   512
#define NST  64
#define LL   2048
#define BB   16
#define NFFT 4096
#define QPITCH 65   // padded row stride for Q to kill smem bank conflicts

// Scratch (sanctioned __device__ globals; no allocation APIs anywhere)
__device__ float  g_f[HH * LL];          // filter taps per head (4 MB)
__device__ float2 g_Fs[HH * NFFT];       // filter spectrum, DIF (bit-rev) order, 1/N baked in (16 MB)

// ---------------------------------------------------------------------------
// Kernel 1: per-head filter f[h][0..L-1] via scalar AR recurrence + 64-block scan
// grid = H blocks, 64 threads
// ---------------------------------------------------------------------------
__global__ __launch_bounds__(NST) void filter_kernel(const float* __restrict__ k) {
    const int h = blockIdx.x;
    const int j = threadIdx.x;  // 0..63

    __shared__ float sh_tmp[NST];
    __shared__ float sh_dd[NST];
    __shared__ float sh_c[NST];
    __shared__ float sh_e[NST];
    __shared__ float Q[NST * QPITCH];            // Q[r][m] at Q[r*QPITCH+m]
    __shared__ float A_s[NST - 1 + LL + 2];      // a_{-63..2048}, left zero pad

    const float kr = k[h * NST + j];
    const float kc = fminf(fmaxf(kr, 1.0f / 16.0f), 1.0f);
    sh_tmp[j] = kc;
    __syncthreads();

    float ssum = 0.0f;
#pragma unroll
    for (int i = 0; i < NST; i++) ssum += sh_tmp[i];
    const float kn = kc / ssum;                  // L1-normalized clipped k
    const float dd = 1.0f / (1.0f + kn);         // subdiagonal of M (cols < 63)
    sh_dd[j] = dd;
    __syncthreads();

    // D[j] = prod_{m<j} dd[m]
    float D = 1.0f;
    for (int m = 0; m < j; m++) D *= sh_dd[m];
    const float w = (j < NST - 1) ? kn * dd : 1.0f;  // top row of M
    sh_c[j] = w * D;   // AR coefficients
    sh_e[j] = kr * D;  // output taps (raw k!)

    // init a array: A_s[63 + i] = a_i; zero pad on the left
    for (int t = j; t < NST - 1 + LL + 2; t += NST) A_s[t] = 0.0f;
    __syncthreads();
    if (j == 0) A_s[NST - 1] = 1.0f;  // a_0 = 1
    // Q[0] = c
    Q[j] = sh_c[j];
    __syncthreads();

    // Build Q: a_{t+1+r} = sum_j Q[r][j] a_{t-j}
    // Q[r][j] = sum_{m=0}^{r-1} c[m]*Q[r-1-m][j] + (j+r<64 ? c[j+r] : 0)
    for (int r = 1; r < NST; r++) {
        float s = (j + r < NST) ? sh_c[j + r] : 0.0f;
        for (int m = 0; m < r; m++) s += sh_c[m] * Q[(r - 1 - m) * QPITCH + j];
        Q[r * QPITCH + j] = s;       // write row r; reads above touch rows < r only
        __syncthreads();
    }

    // Blocked AR scan: 32 chunks of 64 new a-values each; thread j produces a_{t+1+j}
    for (int t = 0; t < LL; t += NST) {
        float s = 0.0f;
#pragma unroll
        for (int m = 0; m < NST; m++) s += Q[j * QPITCH + m] * A_s[NST - 1 + t - m];
        A_s[NST - 1 + t + 1 + j] = s;   // disjoint from read range [.., 63+t]
        __syncthreads();
    }

    // f[i] = sum_n e[n] * a_{i-n}
    for (int i0 = 0; i0 < LL; i0 += NST) {
        const int i = i0 + j;
        float s = 0.0f;
#pragma unroll
        for (int n = 0; n < NST; n++) s += sh_e[n] * A_s[NST - 1 + i - n];
        g_f[h * LL + i] = s;
    }
}

// ---------------------------------------------------------------------------
// FFT helpers: in-place radix-2, 4096-pt, shared memory.
// fft_dif: natural -> bit-reversed, e^{-i} twiddles (Gentleman-Sande)
// fft_dit_inv: bit-reversed -> natural, e^{+i} twiddles (Cooley-Tukey)
// ---------------------------------------------------------------------------
__device__ __forceinline__ void fft_dif(float2* X, int tid, int nthr) {
    for (int s = 12; s >= 1; --s) {
        const int m = 1 << s, half = m >> 1;
        for (int t = tid; t < NFFT / 2; t += nthr) {
            const int jj = t & (half - 1);
            const int g  = t >> (s - 1);
            const int i1 = (g << s) + jj;
            const int i2 = i1 + half;
            const float2 a = X[i1];
            const float2 b = X[i2];
            const float2 dif = make_float2(a.x - b.x, a.y - b.y);
            float sn, cs;
            __sincosf(-6.2831853071795864769f * (float)jj / (float)m, &sn, &cs);
            X[i1] = make_float2(a.x + b.x, a.y + b.y);
            X[i2] = make_float2(dif.x * cs - dif.y * sn, dif.x * sn + dif.y * cs);
        }
        __syncthreads();
    }
}

__device__ __forceinline__ void fft_dit_inv(float2* X, int tid, int nthr) {
    for (int s = 1; s <= 12; ++s) {
        const int m = 1 << s, half = m >> 1;
        for (int t = tid; t < NFFT / 2; t += nthr) {
            const int jj = t & (half - 1);
            const int g  = t >> (s - 1);
            const int i1 = (g << s) + jj;
            const int i2 = i1 + half;
            float sn, cs;
            __sincosf(6.2831853071795864769f * (float)jj / (float)m, &sn, &cs);
            const float2 a = X[i1];
            const float2 b = X[i2];
            const float2 bw = make_float2(b.x * cs - b.y * sn, b.x * sn + b.y * cs);
            X[i1] = make_float2(a.x + bw.x, a.y + bw.y);
            X[i2] = make_float2(a.x - bw.x, a.y - bw.y);
        }
        __syncthreads();
    }
}

// ---------------------------------------------------------------------------
// Kernel 2: filter spectrum per head (DIF order, scaled by 1/N)
// grid = H blocks, 512 threads
// ---------------------------------------------------------------------------
__global__ __launch_bounds__(512) void spec_kernel() {
    __shared__ float2 X[NFFT];
    const int h = blockIdx.x, tid = threadIdx.x, nthr = blockDim.x;
    for (int t = tid; t < NFFT; t += nthr)
        X[t] = make_float2(t < LL ? g_f[h * LL + t] : 0.0f, 0.0f);
    __syncthreads();
    fft_dif(X, tid, nthr);
    const float sc = 1.0f / (float)NFFT;
    for (int t = tid; t < NFFT; t += nthr) {
        const float2 v = X[t];
        g_Fs[h * NFFT + t] = make_float2(v.x * sc, v.y * sc);
    }
}

// ---------------------------------------------------------------------------
// Kernel 3: causal FFT convolution per (b,h) row
// grid = B*H blocks, 512 threads. Pointwise multiply happens in bit-reversed
// order (both spectra share the DIF permutation), so no bit-reversal pass.
// ---------------------------------------------------------------------------
__global__ __launch_bounds__(512) void conv_kernel(const float* __restrict__ u,
                                                   float* __restrict__ y) {
    __shared__ float2 X[NFFT];
    const int row = blockIdx.x;          // b*H + h (matches u row layout)
    const int h   = row & (HH - 1);
    const int tid = threadIdx.x, nthr = blockDim.x;

    const float* ur = u + (size_t)row * LL;
    for (int t = tid; t < NFFT; t += nthr)
        X[t] = make_float2(t < LL ? ur[t] : 0.0f, 0.0f);
    __syncthreads();

    fft_dif(X, tid, nthr);

    const float2* Fs = g_Fs + (size_t)h * NFFT;
    for (int t = tid; t < NFFT; t += nthr) {
        const float2 a = X[t];
        const float2 b = Fs[t];
        X[t] = make_float2(a.x * b.x - a.y * b.y, a.x * b.y + a.y * b.x);
    }
    __syncthreads();

    fft_dit_inv(X, tid, nthr);

    float* yr = y + (size_t)row * LL;
    for (int t = tid; t < LL; t += nthr) yr[t] = X[t].x;
}

// ---------------------------------------------------------------------------
extern "C" void kernel_launch(void* const* d_in, const int* in_sizes, int n_in,
                              void* d_out, int out_size) {
    const float* u;
    const float* k;
    if (in_sizes[0] == BB * HH * LL) {
        u = (const float*)d_in[0];
        k = (const float*)d_in[1];
    } else {
        u = (const float*)d_in[1];
        k = (const float*)d_in[0];
    }
    float* y = (float*)d_out;

    filter_kernel<<<HH, NST>>>(k);
    spec_kernel<<<HH, 512>>>();
    conv_kernel<<<BB * HH, 512>>>(u, y);
}

// round 5
// speedup vs baseline: 2.2663x; 2.2663x over previous
#include <cuda_runtime.h>
#include <math.h>

// Problem constants
#define HH   512
#define NST  64
#define LL   2048
#define BB   16
#define NFFT 4096
#define QPITCH 65   // padded row stride for Q to kill smem bank conflicts
#define CONV_THREADS 512

// Scratch (sanctioned __device__ globals; no allocation APIs anywhere)
__device__ float  g_f[HH * LL];          // filter taps per head (4 MB)
__device__ float2 g_Fs[HH * NFFT];       // filter spectrum, DIF(radix-4) order, 1/N baked in (16 MB)
__device__ float2 g_W[NFFT];             // twiddle table: W[t] = exp(-2*pi*i*t/4096) (32 KB)

// ---------------------------------------------------------------------------
// complex helpers
// ---------------------------------------------------------------------------
__device__ __forceinline__ float2 cadd(float2 a, float2 b) { return make_float2(a.x + b.x, a.y + b.y); }
__device__ __forceinline__ float2 csub(float2 a, float2 b) { return make_float2(a.x - b.x, a.y - b.y); }
__device__ __forceinline__ float2 cmul(float2 a, float2 b) {
    return make_float2(a.x * b.x - a.y * b.y, a.x * b.y + a.y * b.x);
}
__device__ __forceinline__ float2 cmulconj(float2 a, float2 b) {  // a * conj(b)
    return make_float2(a.x * b.x + a.y * b.y, a.y * b.x - a.x * b.y);
}
__device__ __forceinline__ float2 mineg_i(float2 a) { return make_float2(a.y, -a.x); }  // -i*a
__device__ __forceinline__ float2 mul_i(float2 a)   { return make_float2(-a.y, a.x); }  //  i*a

// ---------------------------------------------------------------------------
// Twiddle table init (runs every launch; tiny)
// ---------------------------------------------------------------------------
__global__ void twiddle_kernel() {
    const int t = blockIdx.x * blockDim.x + threadIdx.x;
    if (t < NFFT) {
        float s, c;
        sincosf(-6.2831853071795864769f * (float)t / (float)NFFT, &s, &c);
        g_W[t] = make_float2(c, s);
    }
}

// ---------------------------------------------------------------------------
// Kernel 1: per-head filter f[h][0..L-1] via scalar AR recurrence + 64-block scan
// grid = H blocks, 64 threads
// ---------------------------------------------------------------------------
__global__ __launch_bounds__(NST) void filter_kernel(const float* __restrict__ k) {
    const int h = blockIdx.x;
    const int j = threadIdx.x;  // 0..63

    __shared__ float sh_tmp[NST];
    __shared__ float sh_dd[NST];
    __shared__ float sh_c[NST];
    __shared__ float sh_e[NST];
    __shared__ float Q[NST * QPITCH];            // Q[r][m] at Q[r*QPITCH+m]
    __shared__ float A_s[NST - 1 + LL + 2];      // a_{-63..2048}, left zero pad

    const float kr = k[h * NST + j];
    const float kc = fminf(fmaxf(kr, 1.0f / 16.0f), 1.0f);
    sh_tmp[j] = kc;
    __syncthreads();

    float ssum = 0.0f;
#pragma unroll
    for (int i = 0; i < NST; i++) ssum += sh_tmp[i];
    const float kn = kc / ssum;                  // L1-normalized clipped k
    const float dd = 1.0f / (1.0f + kn);         // subdiagonal of M (cols < 63)
    sh_dd[j] = dd;
    __syncthreads();

    // D[j] = prod_{m<j} dd[m]
    float D = 1.0f;
    for (int m = 0; m < j; m++) D *= sh_dd[m];
    const float w = (j < NST - 1) ? kn * dd : 1.0f;  // top row of M
    sh_c[j] = w * D;   // AR coefficients
    sh_e[j] = kr * D;  // output taps (raw k!)

    // init a array: A_s[63 + i] = a_i; zero pad on the left
    for (int t = j; t < NST - 1 + LL + 2; t += NST) A_s[t] = 0.0f;
    __syncthreads();
    if (j == 0) A_s[NST - 1] = 1.0f;  // a_0 = 1
    // Q[0] = c
    Q[j] = sh_c[j];
    __syncthreads();

    // Build Q: a_{t+1+r} = sum_j Q[r][j] a_{t-j}
    for (int r = 1; r < NST; r++) {
        float s = (j + r < NST) ? sh_c[j + r] : 0.0f;
        for (int m = 0; m < r; m++) s += sh_c[m] * Q[(r - 1 - m) * QPITCH + j];
        Q[r * QPITCH + j] = s;
        __syncthreads();
    }

    // Blocked AR scan: 32 chunks of 64 new a-values each; thread j produces a_{t+1+j}
    for (int t = 0; t < LL; t += NST) {
        float s = 0.0f;
#pragma unroll
        for (int m = 0; m < NST; m++) s += Q[j * QPITCH + m] * A_s[NST - 1 + t - m];
        A_s[NST - 1 + t + 1 + j] = s;
        __syncthreads();
    }

    // f[i] = sum_n e[n] * a_{i-n}
    for (int i0 = 0; i0 < LL; i0 += NST) {
        const int i = i0 + j;
        float s = 0.0f;
#pragma unroll
        for (int n = 0; n < NST; n++) s += sh_e[n] * A_s[NST - 1 + i - n];
        g_f[h * LL + i] = s;
    }
}

// ---------------------------------------------------------------------------
// Radix-4 4096-pt in-place FFT in shared memory (6 stages each way).
// Forward (DIF, e^{-i}): natural -> digit-reversed order.
// Inverse: exact algebraic mirror (stages reversed, conj twiddles),
// digit-reversed -> natural, unnormalized (gain 4 per stage = 4096 total;
// the 1/4096 is baked into the stored filter spectrum).
// Twiddles come from the global table g_W (L1-resident, 32 KB).
// ---------------------------------------------------------------------------
__device__ __forceinline__ void fft4_fwd(float2* X, int tid) {
#pragma unroll
    for (int s = 6; s >= 1; --s) {
        const int q   = 1 << (2 * s - 2);   // quarter of current block size
        const int tsh = 12 - 2 * s;         // twiddle shift
#pragma unroll
        for (int t = tid; t < NFFT / 4; t += CONV_THREADS) {
            const int j    = t & (q - 1);
            const int g    = t >> (2 * s - 2);
            const int base = (g << (2 * s)) + j;
            const float2 x0 = X[base];
            const float2 x1 = X[base + q];
            const float2 x2 = X[base + 2 * q];
            const float2 x3 = X[base + 3 * q];
            const float2 t0 = cadd(x0, x2);
            const float2 t1 = csub(x0, x2);
            const float2 t2 = cadd(x1, x3);
            const float2 t3 = csub(x1, x3);
            const float2 w1 = g_W[j << tsh];
            const float2 w2 = g_W[(2 * j) << tsh];
            const float2 w3 = g_W[(3 * j) << tsh];
            X[base]         = cadd(t0, t2);
            X[base + q]     = cmul(cadd(t1, mineg_i(t3)), w1);  // (t1 - i t3) w^j
            X[base + 2 * q] = cmul(csub(t0, t2), w2);           // (t0 - t2) w^2j
            X[base + 3 * q] = cmul(cadd(t1, mul_i(t3)), w3);    // (t1 + i t3) w^3j
        }
        __syncthreads();
    }
}

__device__ __forceinline__ void fft4_inv(float2* X, int tid) {
#pragma unroll
    for (int s = 1; s <= 6; ++s) {
        const int q   = 1 << (2 * s - 2);
        const int tsh = 12 - 2 * s;
#pragma unroll
        for (int t = tid; t < NFFT / 4; t += CONV_THREADS) {
            const int j    = t & (q - 1);
            const int g    = t >> (2 * s - 2);
            const int base = (g << (2 * s)) + j;
            const float2 y0 = X[base];
            const float2 w1 = g_W[j << tsh];
            const float2 w2 = g_W[(2 * j) << tsh];
            const float2 w3 = g_W[(3 * j) << tsh];
            const float2 y1 = cmulconj(X[base + q],     w1);
            const float2 y2 = cmulconj(X[base + 2 * q], w2);
            const float2 y3 = cmulconj(X[base + 3 * q], w3);
            const float2 A  = cadd(y0, y2);
            const float2 Bm = csub(y0, y2);
            const float2 Cc = cadd(y1, y3);
            const float2 Dd = mul_i(csub(y1, y3));  // i (y1' - y3')
            X[base]         = cadd(A, Cc);
            X[base + q]     = cadd(Bm, Dd);
            X[base + 2 * q] = csub(A, Cc);
            X[base + 3 * q] = csub(Bm, Dd);
        }
        __syncthreads();
    }
}

// ---------------------------------------------------------------------------
// Kernel 2: filter spectrum per head (radix-4 DIF order, scaled by 1/N)
// grid = H blocks, 512 threads
// ---------------------------------------------------------------------------
__global__ __launch_bounds__(CONV_THREADS) void spec_kernel() {
    __shared__ float2 X[NFFT];
    const int h = blockIdx.x, tid = threadIdx.x;
    for (int t = tid; t < NFFT; t += CONV_THREADS)
        X[t] = make_float2(t < LL ? g_f[h * LL + t] : 0.0f, 0.0f);
    __syncthreads();
    fft4_fwd(X, tid);
    const float sc = 1.0f / (float)NFFT;
    for (int t = tid; t < NFFT; t += CONV_THREADS) {
        const float2 v = X[t];
        g_Fs[h * NFFT + t] = make_float2(v.x * sc, v.y * sc);
    }
}

// ---------------------------------------------------------------------------
// Kernel 3: causal FFT convolution, TWO batch rows per CTA.
// Filter is real => conv(u0 + i*u1, f) = y0 + i*y1 exactly.
// grid = (B/2)*H = 4096 blocks, 512 threads.
// Pointwise multiply happens in digit-reversed order (both spectra share
// the same forward permutation), so no reordering pass is needed.
// ---------------------------------------------------------------------------
__global__ __launch_bounds__(CONV_THREADS) void conv_kernel(const float* __restrict__ u,
                                                            float* __restrict__ y) {
    __shared__ float2 X[NFFT];
    const int h   = blockIdx.x & (HH - 1);
    const int p   = blockIdx.x >> 9;       // 0..7
    const int b0  = p;
    const int b1  = p + BB / 2;
    const int tid = threadIdx.x;

    const float* u0 = u + ((size_t)b0 * HH + h) * LL;
    const float* u1 = u + ((size_t)b1 * HH + h) * LL;
    for (int t = tid; t < NFFT; t += CONV_THREADS)
        X[t] = (t < LL) ? make_float2(u0[t], u1[t]) : make_float2(0.0f, 0.0f);
    __syncthreads();

    fft4_fwd(X, tid);

    const float2* Fs = g_Fs + (size_t)h * NFFT;
    for (int t = tid; t < NFFT; t += CONV_THREADS)
        X[t] = cmul(X[t], Fs[t]);
    __syncthreads();

    fft4_inv(X, tid);

    float* y0 = y + ((size_t)b0 * HH + h) * LL;
    float* y1 = y + ((size_t)b1 * HH + h) * LL;
    for (int t = tid; t < LL; t += CONV_THREADS) {
        const float2 v = X[t];
        y0[t] = v.x;
        y1[t] = v.y;
    }
}

// ---------------------------------------------------------------------------
extern "C" void kernel_launch(void* const* d_in, const int* in_sizes, int n_in,
                              void* d_out, int out_size) {
    const float* u;
    const float* k;
    if (in_sizes[0] == BB * HH * LL) {
        u = (const float*)d_in[0];
        k = (const float*)d_in[1];
    } else {
        u = (const float*)d_in[1];
        k = (const float*)d_in[0];
    }
    float* y = (float*)d_out;

    twiddle_kernel<<<NFFT / 256, 256>>>();
    filter_kernel<<<HH, NST>>>(k);
    spec_kernel<<<HH, CONV_THREADS>>>();
    conv_kernel<<<(BB / 2) * HH, CONV_THREADS>>>(u, y);
}

// round 6
// speedup vs baseline: 3.2612x; 1.4390x over previous
#include <cuda_runtime.h>
#include <math.h>

// Problem constants
#define HH   512
#define NST  64
#define LL   2048
#define BB   16
#define NFFT 4096
#define QPITCH 65

// Scratch (sanctioned __device__ globals; no allocation APIs anywhere)
__device__ float  g_f[HH * LL];          // filter taps per head (4 MB)
__device__ float2 g_Fs[HH * NFFT];       // filter spectrum, permuted order, 1/N baked in (16 MB)
__device__ float2 g_W[NFFT];             // twiddle table: W[t] = exp(-2*pi*i*t/4096)

// ---------------------------------------------------------------------------
// complex helpers
// ---------------------------------------------------------------------------
__device__ __forceinline__ float2 cadd(float2 a, float2 b) { return make_float2(a.x + b.x, a.y + b.y); }
__device__ __forceinline__ float2 csub(float2 a, float2 b) { return make_float2(a.x - b.x, a.y - b.y); }
__device__ __forceinline__ float2 cmul(float2 a, float2 b) {
    return make_float2(a.x * b.x - a.y * b.y, a.x * b.y + a.y * b.x);
}
__device__ __forceinline__ float2 cmulconj(float2 a, float2 b) {  // a * conj(b)
    return make_float2(a.x * b.x + a.y * b.y, a.y * b.x - a.x * b.y);
}

// ---------------------------------------------------------------------------
// Radix-8 butterfly in registers. FWD: e^{-2pi i/8} twiddles; !FWD: conjugate
// (unnormalized inverse: dft8<false>(dft8<true>(x)) = 8*x).
// ---------------------------------------------------------------------------
template <bool FWD>
__device__ __forceinline__ void dft8(float2 v[8]) {
    const float C = 0.70710678118654752440f;
    float2 s0 = cadd(v[0], v[4]), d0 = csub(v[0], v[4]);
    float2 s1 = cadd(v[1], v[5]), d1 = csub(v[1], v[5]);
    float2 s2 = cadd(v[2], v[6]), d2 = csub(v[2], v[6]);
    float2 s3 = cadd(v[3], v[7]), d3 = csub(v[3], v[7]);
    // even half (x0,x2,x4,x6)
    float2 E0 = cadd(s0, s2), E2 = csub(s0, s2);
    float2 jd2 = FWD ? make_float2(d2.y, -d2.x) : make_float2(-d2.y, d2.x);
    float2 E1 = cadd(d0, jd2);
    float2 E3 = csub(d0, jd2);
    // odd half (x1,x3,x5,x7)
    float2 O0 = cadd(s1, s3), O2 = csub(s1, s3);
    float2 jd3 = FWD ? make_float2(d3.y, -d3.x) : make_float2(-d3.y, d3.x);
    float2 O1 = cadd(d1, jd3), O3 = csub(d1, jd3);
    // odd twiddles: w^1, w^2, w^3
    float2 tO1 = FWD ? make_float2(C * (O1.x + O1.y), C * (O1.y - O1.x))
                     : make_float2(C * (O1.x - O1.y), C * (O1.y + O1.x));
    float2 tO2 = FWD ? make_float2(O2.y, -O2.x) : make_float2(-O2.y, O2.x);
    float2 tO3 = FWD ? make_float2(C * (O3.y - O3.x), -C * (O3.x + O3.y))
                     : make_float2(-C * (O3.x + O3.y), C * (O3.x - O3.y));
    v[0] = cadd(E0, O0);  v[4] = csub(E0, O0);
    v[1] = cadd(E1, tO1); v[5] = csub(E1, tO1);
    v[2] = cadd(E2, tO2); v[6] = csub(E2, tO2);
    v[3] = cadd(E3, tO3); v[7] = csub(E3, tO3);
}

// ---------------------------------------------------------------------------
// Twiddle table init
// ---------------------------------------------------------------------------
__global__ void twiddle_kernel() {
    const int t = blockIdx.x * blockDim.x + threadIdx.x;
    if (t < NFFT) {
        float s, c;
        sincosf(-6.2831853071795864769f * (float)t / (float)NFFT, &s, &c);
        g_W[t] = make_float2(c, s);
    }
}

// ---------------------------------------------------------------------------
// Kernel 1: per-head filter via scalar AR recurrence + 64-block scan (unchanged)
// ---------------------------------------------------------------------------
__global__ __launch_bounds__(NST) void filter_kernel(const float* __restrict__ k) {
    const int h = blockIdx.x;
    const int j = threadIdx.x;

    __shared__ float sh_tmp[NST];
    __shared__ float sh_dd[NST];
    __shared__ float sh_c[NST];
    __shared__ float sh_e[NST];
    __shared__ float Q[NST * QPITCH];
    __shared__ float A_s[NST - 1 + LL + 2];

    const float kr = k[h * NST + j];
    const float kc = fminf(fmaxf(kr, 1.0f / 16.0f), 1.0f);
    sh_tmp[j] = kc;
    __syncthreads();

    float ssum = 0.0f;
#pragma unroll
    for (int i = 0; i < NST; i++) ssum += sh_tmp[i];
    const float kn = kc / ssum;
    const float dd = 1.0f / (1.0f + kn);
    sh_dd[j] = dd;
    __syncthreads();

    float D = 1.0f;
    for (int m = 0; m < j; m++) D *= sh_dd[m];
    const float w = (j < NST - 1) ? kn * dd : 1.0f;
    sh_c[j] = w * D;
    sh_e[j] = kr * D;

    for (int t = j; t < NST - 1 + LL + 2; t += NST) A_s[t] = 0.0f;
    __syncthreads();
    if (j == 0) A_s[NST - 1] = 1.0f;
    Q[j] = sh_c[j];
    __syncthreads();

    for (int r = 1; r < NST; r++) {
        float s = (j + r < NST) ? sh_c[j + r] : 0.0f;
        for (int m = 0; m < r; m++) s += sh_c[m] * Q[(r - 1 - m) * QPITCH + j];
        Q[r * QPITCH + j] = s;
        __syncthreads();
    }

    for (int t = 0; t < LL; t += NST) {
        float s = 0.0f;
#pragma unroll
        for (int m = 0; m < NST; m++) s += Q[j * QPITCH + m] * A_s[NST - 1 + t - m];
        A_s[NST - 1 + t + 1 + j] = s;
        __syncthreads();
    }

    for (int i0 = 0; i0 < LL; i0 += NST) {
        const int i = i0 + j;
        float s = 0.0f;
#pragma unroll
        for (int n = 0; n < NST; n++) s += sh_e[n] * A_s[NST - 1 + i - n];
        g_f[h * LL + i] = s;
    }
}

// ===========================================================================
// Register-resident radix-8 4096-pt FFT, 512 threads, 8 points/thread.
// Thread coords: t = m*64 + m'*8 + n3 ; n2 = t&63.
// Exchanges use XOR swizzles -> all LDS/STS phases conflict-free.
// Forward output: thread t holds permuted slots 8t+j (j=0..7).
// ===========================================================================

// Forward pipeline: v[] holds x[t + 512 r] on entry; permuted spectrum on exit.
#define FFT8_FWD_BODY(S, t, m, mp, n3, n2, v)                                   \
    {                                                                           \
        dft8<true>(v);                                                          \
        _Pragma("unroll") for (int j = 1; j < 8; j++)                           \
            v[j] = cmul(v[j], g_W[t * j]);                                      \
        _Pragma("unroll") for (int j = 0; j < 8; j++)                           \
            S[(j << 9) + t] = v[j];                                             \
        __syncthreads();                                                        \
        _Pragma("unroll") for (int r = 0; r < 8; r++)                           \
            v[r] = S[(m << 9) + n2 + (r << 6)];                                 \
        __syncthreads();                                                        \
        dft8<true>(v);                                                          \
        _Pragma("unroll") for (int j = 1; j < 8; j++)                           \
            v[j] = cmul(v[j], g_W[(n2 * j) << 3]);                              \
        _Pragma("unroll") for (int j = 0; j < 8; j++)                           \
            S[(m << 9) + (j << 6) + (n2 ^ (j << 3))] = v[j];                    \
        __syncthreads();                                                        \
        _Pragma("unroll") for (int r = 0; r < 8; r++)                           \
            v[r] = S[(m << 9) + (mp << 6) + ((r ^ mp) << 3) + n3];              \
        __syncthreads();                                                        \
        dft8<true>(v);                                                          \
        _Pragma("unroll") for (int j = 1; j < 8; j++)                           \
            v[j] = cmul(v[j], g_W[(n3 * j) << 6]);                              \
        _Pragma("unroll") for (int j = 0; j < 8; j++)                           \
            S[(n3 << 9) + (t & 504) + (j ^ n3)] = v[j];                         \
        __syncthreads();                                                        \
        _Pragma("unroll") for (int j = 0; j < 8; j++)                           \
            v[j] = S[(j << 9) + (t & 504) + ((t & 7) ^ j)];                     \
        dft8<true>(v);                                                          \
    }

// Inverse pipeline: exact mirror. v[] holds permuted slots 8t+j on entry;
// x[t + 512 r] * 4096 on exit (scale baked into g_Fs).
#define FFT8_INV_BODY(S, t, m, mp, n3, n2, v)                                   \
    {                                                                           \
        dft8<false>(v);                                                         \
        /* writes hit exactly this thread's own stage-D read addrs: race-free */\
        _Pragma("unroll") for (int j = 0; j < 8; j++)                           \
            S[(j << 9) + (t & 504) + ((t & 7) ^ j)] = v[j];                     \
        __syncthreads();                                                        \
        _Pragma("unroll") for (int j = 0; j < 8; j++)                           \
            v[j] = S[(n3 << 9) + (t & 504) + (j ^ n3)];                         \
        __syncthreads();                                                        \
        _Pragma("unroll") for (int j = 1; j < 8; j++)                           \
            v[j] = cmulconj(v[j], g_W[(n3 * j) << 6]);                          \
        dft8<false>(v);                                                         \
        _Pragma("unroll") for (int r = 0; r < 8; r++)                           \
            S[(m << 9) + (mp << 6) + ((r ^ mp) << 3) + n3] = v[r];              \
        __syncthreads();                                                        \
        _Pragma("unroll") for (int j = 0; j < 8; j++)                           \
            v[j] = S[(m << 9) + (j << 6) + (n2 ^ (j << 3))];                    \
        __syncthreads();                                                        \
        _Pragma("unroll") for (int j = 1; j < 8; j++)                           \
            v[j] = cmulconj(v[j], g_W[(n2 * j) << 3]);                          \
        dft8<false>(v);                                                         \
        _Pragma("unroll") for (int r = 0; r < 8; r++)                           \
            S[(m << 9) + n2 + (r << 6)] = v[r];                                 \
        __syncthreads();                                                        \
        _Pragma("unroll") for (int j = 0; j < 8; j++)                           \
            v[j] = S[(j << 9) + t];                                             \
        _Pragma("unroll") for (int j = 1; j < 8; j++)                           \
            v[j] = cmulconj(v[j], g_W[t * j]);                                  \
        dft8<false>(v);                                                         \
    }

// ---------------------------------------------------------------------------
// Kernel 2: filter spectrum per head, radix-8 forward (order matches conv)
// grid = H blocks, 512 threads
// ---------------------------------------------------------------------------
__global__ __launch_bounds__(512, 2) void spec_kernel() {
    __shared__ float2 S[NFFT];
    const int t = threadIdx.x;
    const int m = t >> 6, mp = (t >> 3) & 7, n3 = t & 7, n2 = t & 63;
    const int h = blockIdx.x;

    float2 v[8];
    const float* fr = g_f + (size_t)h * LL;
#pragma unroll
    for (int r = 0; r < 8; r++)
        v[r] = (r < 4) ? make_float2(fr[t + 512 * r], 0.0f) : make_float2(0.0f, 0.0f);

    FFT8_FWD_BODY(S, t, m, mp, n3, n2, v);

    const float sc = 1.0f / (float)NFFT;
    float2* out = g_Fs + (size_t)h * NFFT + 8 * t;
#pragma unroll
    for (int j = 0; j < 8; j++)
        out[j] = make_float2(v[j].x * sc, v[j].y * sc);
}

// ---------------------------------------------------------------------------
// Kernel 3: causal FFT convolution, TWO batch rows per CTA (real filter =>
// conv(u0 + i*u1, f) = y0 + i*y1 exactly). grid = (B/2)*H = 4096, 512 thr.
// ---------------------------------------------------------------------------
__global__ __launch_bounds__(512, 2) void conv_kernel(const float* __restrict__ u,
                                                      float* __restrict__ y) {
    __shared__ float2 S[NFFT];
    const int t = threadIdx.x;
    const int m = t >> 6, mp = (t >> 3) & 7, n3 = t & 7, n2 = t & 63;
    const int h = blockIdx.x & (HH - 1);
    const int p = blockIdx.x >> 9;  // 0..7

    const float* u0 = u + ((size_t)p * HH + h) * LL;
    const float* u1 = u + ((size_t)(p + BB / 2) * HH + h) * LL;

    float2 v[8];
#pragma unroll
    for (int r = 0; r < 8; r++)
        v[r] = (r < 4) ? make_float2(u0[t + 512 * r], u1[t + 512 * r])
                       : make_float2(0.0f, 0.0f);

    FFT8_FWD_BODY(S, t, m, mp, n3, n2, v);

    // pointwise multiply in registers (coalesced float4 spectrum reads)
    const float4* F4 = reinterpret_cast<const float4*>(g_Fs + (size_t)h * NFFT) + 4 * t;
#pragma unroll
    for (int jj = 0; jj < 4; jj++) {
        const float4 f = F4[jj];
        v[2 * jj]     = cmul(v[2 * jj],     make_float2(f.x, f.y));
        v[2 * jj + 1] = cmul(v[2 * jj + 1], make_float2(f.z, f.w));
    }

    FFT8_INV_BODY(S, t, m, mp, n3, n2, v);

    float* y0 = y + ((size_t)p * HH + h) * LL;
    float* y1 = y + ((size_t)(p + BB / 2) * HH + h) * LL;
#pragma unroll
    for (int r = 0; r < 4; r++) {
        y0[t + 512 * r] = v[r].x;
        y1[t + 512 * r] = v[r].y;
    }
}

// ---------------------------------------------------------------------------
extern "C" void kernel_launch(void* const* d_in, const int* in_sizes, int n_in,
                              void* d_out, int out_size) {
    const float* u;
    const float* k;
    if (in_sizes[0] == BB * HH * LL) {
        u = (const float*)d_in[0];
        k = (const float*)d_in[1];
    } else {
        u = (const float*)d_in[1];
        k = (const float*)d_in[0];
    }
    float* y = (float*)d_out;

    twiddle_kernel<<<NFFT / 256, 256>>>();
    filter_kernel<<<HH, NST>>>(k);
    spec_kernel<<<HH, 512>>>();
    conv_kernel<<<(BB / 2) * HH, 512>>>(u, y);
}

// round 7
// speedup vs baseline: 6.1501x; 1.8858x over previous
#include <cuda_runtime.h>
#include <math.h>

// Problem constants
#define HH   512
#define NST  64
#define LL   2048
#define BB   16
#define NFFT 4096
#define QPITCH 65

// Scratch (sanctioned __device__ globals; no allocation APIs anywhere)
__device__ float  g_f[HH * LL];          // filter taps per head (4 MB)
__device__ float2 g_Fs[HH * NFFT];       // filter spectrum, permuted order, 1/N baked in (16 MB)
__device__ float2 g_W1[512];             // w^t,      t=0..511   (w = e^{-2pi i/4096})
__device__ float2 g_W2[64];              // w^{8n},   n=0..63
__device__ float2 g_W3[8];               // w^{64n},  n=0..7

// ---------------------------------------------------------------------------
// complex helpers
// ---------------------------------------------------------------------------
__device__ __forceinline__ float2 cadd(float2 a, float2 b) { return make_float2(a.x + b.x, a.y + b.y); }
__device__ __forceinline__ float2 csub(float2 a, float2 b) { return make_float2(a.x - b.x, a.y - b.y); }
__device__ __forceinline__ float2 cmul(float2 a, float2 b) {
    return make_float2(a.x * b.x - a.y * b.y, a.x * b.y + a.y * b.x);
}
__device__ __forceinline__ float2 cmulconj(float2 a, float2 b) {  // a * conj(b)
    return make_float2(a.x * b.x + a.y * b.y, a.y * b.x - a.x * b.y);
}

// Twiddle application from a single base value b: v[j] *= b^j (or conj for INV).
// Powers built with a log-depth multiply chain — no memory traffic.
#define TWIDDLE_FWD(v, bexpr)                                                   \
    {                                                                           \
        const float2 b_ = (bexpr);                                              \
        const float2 w2_ = cmul(b_, b_);                                        \
        const float2 w3_ = cmul(w2_, b_);                                       \
        const float2 w4_ = cmul(w2_, w2_);                                      \
        v[1] = cmul(v[1], b_);  v[2] = cmul(v[2], w2_);                         \
        v[3] = cmul(v[3], w3_); v[4] = cmul(v[4], w4_);                         \
        v[5] = cmul(v[5], cmul(w4_, b_));                                       \
        v[6] = cmul(v[6], cmul(w4_, w2_));                                      \
        v[7] = cmul(v[7], cmul(w4_, w3_));                                      \
    }

#define TWIDDLE_INV(v, bexpr)                                                   \
    {                                                                           \
        const float2 b_ = (bexpr);                                              \
        const float2 w2_ = cmul(b_, b_);                                        \
        const float2 w3_ = cmul(w2_, b_);                                       \
        const float2 w4_ = cmul(w2_, w2_);                                      \
        v[1] = cmulconj(v[1], b_);  v[2] = cmulconj(v[2], w2_);                 \
        v[3] = cmulconj(v[3], w3_); v[4] = cmulconj(v[4], w4_);                 \
        v[5] = cmulconj(v[5], cmul(w4_, b_));                                   \
        v[6] = cmulconj(v[6], cmul(w4_, w2_));                                  \
        v[7] = cmulconj(v[7], cmul(w4_, w3_));                                  \
    }

// ---------------------------------------------------------------------------
// Radix-8 butterfly in registers. FWD: e^{-2pi i/8} twiddles; !FWD: conjugate
// ---------------------------------------------------------------------------
template <bool FWD>
__device__ __forceinline__ void dft8(float2 v[8]) {
    const float C = 0.70710678118654752440f;
    float2 s0 = cadd(v[0], v[4]), d0 = csub(v[0], v[4]);
    float2 s1 = cadd(v[1], v[5]), d1 = csub(v[1], v[5]);
    float2 s2 = cadd(v[2], v[6]), d2 = csub(v[2], v[6]);
    float2 s3 = cadd(v[3], v[7]), d3 = csub(v[3], v[7]);
    float2 E0 = cadd(s0, s2), E2 = csub(s0, s2);
    float2 jd2 = FWD ? make_float2(d2.y, -d2.x) : make_float2(-d2.y, d2.x);
    float2 E1 = cadd(d0, jd2);
    float2 E3 = csub(d0, jd2);
    float2 O0 = cadd(s1, s3), O2 = csub(s1, s3);
    float2 jd3 = FWD ? make_float2(d3.y, -d3.x) : make_float2(-d3.y, d3.x);
    float2 O1 = cadd(d1, jd3), O3 = csub(d1, jd3);
    float2 tO1 = FWD ? make_float2(C * (O1.x + O1.y), C * (O1.y - O1.x))
                     : make_float2(C * (O1.x - O1.y), C * (O1.y + O1.x));
    float2 tO2 = FWD ? make_float2(O2.y, -O2.x) : make_float2(-O2.y, O2.x);
    float2 tO3 = FWD ? make_float2(C * (O3.y - O3.x), -C * (O3.x + O3.y))
                     : make_float2(-C * (O3.x + O3.y), C * (O3.x - O3.y));
    v[0] = cadd(E0, O0);  v[4] = csub(E0, O0);
    v[1] = cadd(E1, tO1); v[5] = csub(E1, tO1);
    v[2] = cadd(E2, tO2); v[6] = csub(E2, tO2);
    v[3] = cadd(E3, tO3); v[7] = csub(E3, tO3);
}

// ---------------------------------------------------------------------------
// Twiddle table init
// ---------------------------------------------------------------------------
__global__ void twiddle_kernel() {
    const int t = blockIdx.x * blockDim.x + threadIdx.x;
    const float TWO_PI = 6.2831853071795864769f;
    if (t < 512) {
        float s, c;
        sincosf(-TWO_PI * (float)t / (float)NFFT, &s, &c);
        g_W1[t] = make_float2(c, s);
    }
    if (t < 64) {
        float s, c;
        sincosf(-TWO_PI * (float)(8 * t) / (float)NFFT, &s, &c);
        g_W2[t] = make_float2(c, s);
    }
    if (t < 8) {
        float s, c;
        sincosf(-TWO_PI * (float)(64 * t) / (float)NFFT, &s, &c);
        g_W3[t] = make_float2(c, s);
    }
}

// ---------------------------------------------------------------------------
// Kernel 1: per-head filter via scalar AR recurrence + 64-block scan.
// Q row and e-taps register-resident; 4 accumulators break latency chains.
// ---------------------------------------------------------------------------
__global__ __launch_bounds__(NST) void filter_kernel(const float* __restrict__ k) {
    const int h = blockIdx.x;
    const int j = threadIdx.x;

    __shared__ float sh_tmp[NST];
    __shared__ float sh_dd[NST];
    __shared__ float sh_c[NST];
    __shared__ float sh_e[NST];
    __shared__ float Q[NST * QPITCH];
    __shared__ float A_s[NST - 1 + LL + 2];

    const float kr = k[h * NST + j];
    const float kc = fminf(fmaxf(kr, 1.0f / 16.0f), 1.0f);
    sh_tmp[j] = kc;
    __syncthreads();

    float ssum = 0.0f;
#pragma unroll
    for (int i = 0; i < NST; i++) ssum += sh_tmp[i];
    const float kn = kc / ssum;
    const float dd = 1.0f / (1.0f + kn);
    sh_dd[j] = dd;
    __syncthreads();

    float D = 1.0f;
    for (int m = 0; m < j; m++) D *= sh_dd[m];
    const float w = (j < NST - 1) ? kn * dd : 1.0f;
    sh_c[j] = w * D;
    sh_e[j] = kr * D;

    for (int t = j; t < NST - 1 + LL + 2; t += NST) A_s[t] = 0.0f;
    __syncthreads();
    if (j == 0) A_s[NST - 1] = 1.0f;
    Q[j] = sh_c[j];
    __syncthreads();

    // Build Q: Q[r][j] = sum_{m<r} c[m] Q[r-1-m][j] + (j+r<64 ? c[j+r] : 0)
    for (int r = 1; r < NST; r++) {
        float s0 = (j + r < NST) ? sh_c[j + r] : 0.0f;
        float s1 = 0.0f;
        int m = 0;
        for (; m + 1 < r; m += 2) {
            s0 += sh_c[m]     * Q[(r - 1 - m) * QPITCH + j];
            s1 += sh_c[m + 1] * Q[(r - 2 - m) * QPITCH + j];
        }
        if (m < r) s0 += sh_c[m] * Q[(r - 1 - m) * QPITCH + j];
        Q[r * QPITCH + j] = s0 + s1;
        __syncthreads();
    }

    // My Q row -> registers (constant indices, fully unrolled)
    float qr[NST];
#pragma unroll
    for (int m = 0; m < NST; m++) qr[m] = Q[j * QPITCH + m];

    // Blocked AR scan: thread j produces a_{t+1+j}; A_s reads are broadcasts.
    for (int t = 0; t < LL; t += NST) {
        const float* Ab = &A_s[NST - 1 + t];
        float s0 = 0.0f, s1 = 0.0f, s2 = 0.0f, s3 = 0.0f;
#pragma unroll
        for (int m = 0; m < NST; m += 4) {
            s0 += qr[m]     * Ab[-m];
            s1 += qr[m + 1] * Ab[-m - 1];
            s2 += qr[m + 2] * Ab[-m - 2];
            s3 += qr[m + 3] * Ab[-m - 3];
        }
        A_s[NST + t + j] = (s0 + s1) + (s2 + s3);
        __syncthreads();
    }

    // f[i] = sum_n e[n] * a_{i-n}, e-taps register-resident
    float er[NST];
#pragma unroll
    for (int n = 0; n < NST; n++) er[n] = sh_e[n];

    for (int i0 = 0; i0 < LL; i0 += NST) {
        const int i = i0 + j;
        const float* Ab = &A_s[NST - 1 + i];
        float s0 = 0.0f, s1 = 0.0f, s2 = 0.0f, s3 = 0.0f;
#pragma unroll
        for (int n = 0; n < NST; n += 4) {
            s0 += er[n]     * Ab[-n];
            s1 += er[n + 1] * Ab[-n - 1];
            s2 += er[n + 2] * Ab[-n - 2];
            s3 += er[n + 3] * Ab[-n - 3];
        }
        g_f[h * LL + i] = (s0 + s1) + (s2 + s3);
    }
}

// ===========================================================================
// Register-resident radix-8 4096-pt FFT, 512 threads, 8 points/thread.
// Thread coords: t = m*64 + m'*8 + n3 ; n2 = t&63.
// Exchanges use XOR swizzles -> all LDS/STS phases conflict-free.
// Twiddles: one base load per stage + in-register power chain.
// ===========================================================================

#define FFT8_FWD_BODY(S, t, m, mp, n3, n2, v)                                   \
    {                                                                           \
        dft8<true>(v);                                                          \
        TWIDDLE_FWD(v, g_W1[t]);                                                \
        _Pragma("unroll") for (int j = 0; j < 8; j++)                           \
            S[(j << 9) + t] = v[j];                                             \
        __syncthreads();                                                        \
        _Pragma("unroll") for (int r = 0; r < 8; r++)                           \
            v[r] = S[(m << 9) + n2 + (r << 6)];                                 \
        __syncthreads();                                                        \
        dft8<true>(v);                                                          \
        TWIDDLE_FWD(v, g_W2[n2]);                                               \
        _Pragma("unroll") for (int j = 0; j < 8; j++)                           \
            S[(m << 9) + (j << 6) + (n2 ^ (j << 3))] = v[j];                    \
        __syncthreads();                                                        \
        _Pragma("unroll") for (int r = 0; r < 8; r++)                           \
            v[r] = S[(m << 9) + (mp << 6) + ((r ^ mp) << 3) + n3];              \
        __syncthreads();                                                        \
        dft8<true>(v);                                                          \
        TWIDDLE_FWD(v, g_W3[n3]);                                               \
        _Pragma("unroll") for (int j = 0; j < 8; j++)                           \
            S[(n3 << 9) + (t & 504) + (j ^ n3)] = v[j];                         \
        __syncthreads();                                                        \
        _Pragma("unroll") for (int j = 0; j < 8; j++)                           \
            v[j] = S[(j << 9) + (t & 504) + ((t & 7) ^ j)];                     \
        dft8<true>(v);                                                          \
    }

#define FFT8_INV_BODY(S, t, m, mp, n3, n2, v)                                   \
    {                                                                           \
        dft8<false>(v);                                                         \
        /* writes hit exactly this thread's own stage-D read addrs: race-free */\
        _Pragma("unroll") for (int j = 0; j < 8; j++)                           \
            S[(j << 9) + (t & 504) + ((t & 7) ^ j)] = v[j];                     \
        __syncthreads();                                                        \
        _Pragma("unroll") for (int j = 0; j < 8; j++)                           \
            v[j] = S[(n3 << 9) + (t & 504) + (j ^ n3)];                         \
        __syncthreads();                                                        \
        TWIDDLE_INV(v, g_W3[n3]);                                               \
        dft8<false>(v);                                                         \
        _Pragma("unroll") for (int r = 0; r < 8; r++)                           \
            S[(m << 9) + (mp << 6) + ((r ^ mp) << 3) + n3] = v[r];              \
        __syncthreads();                                                        \
        _Pragma("unroll") for (int j = 0; j < 8; j++)                           \
            v[j] = S[(m << 9) + (j << 6) + (n2 ^ (j << 3))];                    \
        __syncthreads();                                                        \
        TWIDDLE_INV(v, g_W2[n2]);                                               \
        dft8<false>(v);                                                         \
        _Pragma("unroll") for (int r = 0; r < 8; r++)                           \
            S[(m << 9) + n2 + (r << 6)] = v[r];                                 \
        __syncthreads();                                                        \
        _Pragma("unroll") for (int j = 0; j < 8; j++)                           \
            v[j] = S[(j << 9) + t];                                             \
        TWIDDLE_INV(v, g_W1[t]);                                                \
        dft8<false>(v);                                                         \
    }

// ---------------------------------------------------------------------------
// Kernel 2: filter spectrum per head, radix-8 forward (order matches conv)
// ---------------------------------------------------------------------------
__global__ __launch_bounds__(512, 2) void spec_kernel() {
    __shared__ float2 S[NFFT];
    const int t = threadIdx.x;
    const int m = t >> 6, mp = (t >> 3) & 7, n3 = t & 7, n2 = t & 63;
    const int h = blockIdx.x;

    float2 v[8];
    const float* fr = g_f + (size_t)h * LL;
#pragma unroll
    for (int r = 0; r < 8; r++)
        v[r] = (r < 4) ? make_float2(fr[t + 512 * r], 0.0f) : make_float2(0.0f, 0.0f);

    FFT8_FWD_BODY(S, t, m, mp, n3, n2, v);

    const float sc = 1.0f / (float)NFFT;
    float2* out = g_Fs + (size_t)h * NFFT + 8 * t;
#pragma unroll
    for (int j = 0; j < 8; j++)
        out[j] = make_float2(v[j].x * sc, v[j].y * sc);
}

// ---------------------------------------------------------------------------
// Kernel 3: causal FFT convolution, TWO batch rows per CTA (real filter =>
// conv(u0 + i*u1, f) = y0 + i*y1 exactly). grid = (B/2)*H = 4096, 512 thr.
// ---------------------------------------------------------------------------
__global__ __launch_bounds__(512, 2) void conv_kernel(const float* __restrict__ u,
                                                      float* __restrict__ y) {
    __shared__ float2 S[NFFT];
    const int t = threadIdx.x;
    const int m = t >> 6, mp = (t >> 3) & 7, n3 = t & 7, n2 = t & 63;
    const int h = blockIdx.x & (HH - 1);
    const int p = blockIdx.x >> 9;  // 0..7

    const float* u0 = u + ((size_t)p * HH + h) * LL;
    const float* u1 = u + ((size_t)(p + BB / 2) * HH + h) * LL;

    float2 v[8];
#pragma unroll
    for (int r = 0; r < 8; r++)
        v[r] = (r < 4) ? make_float2(u0[t + 512 * r], u1[t + 512 * r])
                       : make_float2(0.0f, 0.0f);

    FFT8_FWD_BODY(S, t, m, mp, n3, n2, v);

    // pointwise multiply in registers (coalesced float4 spectrum reads)
    const float4* F4 = reinterpret_cast<const float4*>(g_Fs + (size_t)h * NFFT) + 4 * t;
#pragma unroll
    for (int jj = 0; jj < 4; jj++) {
        const float4 f = __ldg(&F4[jj]);
        v[2 * jj]     = cmul(v[2 * jj],     make_float2(f.x, f.y));
        v[2 * jj + 1] = cmul(v[2 * jj + 1], make_float2(f.z, f.w));
    }

    FFT8_INV_BODY(S, t, m, mp, n3, n2, v);

    float* y0 = y + ((size_t)p * HH + h) * LL;
    float* y1 = y + ((size_t)(p + BB / 2) * HH + h) * LL;
#pragma unroll
    for (int r = 0; r < 4; r++) {
        y0[t + 512 * r] = v[r].x;
        y1[t + 512 * r] = v[r].y;
    }
}

// ---------------------------------------------------------------------------
extern "C" void kernel_launch(void* const* d_in, const int* in_sizes, int n_in,
                              void* d_out, int out_size) {
    const float* u;
    const float* k;
    if (in_sizes[0] == BB * HH * LL) {
        u = (const float*)d_in[0];
        k = (const float*)d_in[1];
    } else {
        u = (const float*)d_in[1];
        k = (const float*)d_in[0];
    }
    float* y = (float*)d_out;

    twiddle_kernel<<<2, 256>>>();
    filter_kernel<<<HH, NST>>>(k);
    spec_kernel<<<HH, 512>>>();
    conv_kernel<<<(BB / 2) * HH, 512>>>(u, y);
}

// round 9
// speedup vs baseline: 6.3224x; 1.0280x over previous
#include <cuda_runtime.h>
#include <math.h>

// Problem constants
#define HH   512
#define NST  64
#define LL   2048
#define BB   16
#define NFFT 4096
#define QPITCH 65
#define ASZ  (NST - 1 + LL + 2)

// Scratch (sanctioned __device__ globals; no allocation APIs anywhere)
__device__ float2 g_Fs[HH * NFFT];       // filter spectrum, permuted order, 1/N baked in (16 MB)
__device__ float2 g_W1[512];             // w^t,      t=0..511   (w = e^{-2pi i/4096})
__device__ float2 g_W2[64];              // w^{8n},   n=0..63
__device__ float2 g_W3[8];               // w^{64n},  n=0..7

// ---------------------------------------------------------------------------
// complex helpers
// ---------------------------------------------------------------------------
__device__ __forceinline__ float2 cadd(float2 a, float2 b) { return make_float2(a.x + b.x, a.y + b.y); }
__device__ __forceinline__ float2 csub(float2 a, float2 b) { return make_float2(a.x - b.x, a.y - b.y); }
__device__ __forceinline__ float2 cmul(float2 a, float2 b) {
    return make_float2(a.x * b.x - a.y * b.y, a.x * b.y + a.y * b.x);
}
__device__ __forceinline__ float2 cmulconj(float2 a, float2 b) {  // a * conj(b)
    return make_float2(a.x * b.x + a.y * b.y, a.y * b.x - a.x * b.y);
}

// Twiddle application from a single base value b: v[j] *= b^j (or conj for INV).
#define TWIDDLE_FWD(v, bexpr)                                                   \
    {                                                                           \
        const float2 b_ = (bexpr);                                              \
        const float2 w2_ = cmul(b_, b_);                                        \
        const float2 w3_ = cmul(w2_, b_);                                       \
        const float2 w4_ = cmul(w2_, w2_);                                      \
        v[1] = cmul(v[1], b_);  v[2] = cmul(v[2], w2_);                         \
        v[3] = cmul(v[3], w3_); v[4] = cmul(v[4], w4_);                         \
        v[5] = cmul(v[5], cmul(w4_, b_));                                       \
        v[6] = cmul(v[6], cmul(w4_, w2_));                                      \
        v[7] = cmul(v[7], cmul(w4_, w3_));                                      \
    }

#define TWIDDLE_INV(v, bexpr)                                                   \
    {                                                                           \
        const float2 b_ = (bexpr);                                              \
        const float2 w2_ = cmul(b_, b_);                                        \
        const float2 w3_ = cmul(w2_, b_);                                       \
        const float2 w4_ = cmul(w2_, w2_);                                      \
        v[1] = cmulconj(v[1], b_);  v[2] = cmulconj(v[2], w2_);                 \
        v[3] = cmulconj(v[3], w3_); v[4] = cmulconj(v[4], w4_);                 \
        v[5] = cmulconj(v[5], cmul(w4_, b_));                                   \
        v[6] = cmulconj(v[6], cmul(w4_, w2_));                                  \
        v[7] = cmulconj(v[7], cmul(w4_, w3_));                                  \
    }

// ---------------------------------------------------------------------------
// Radix-8 butterfly in registers. FWD: e^{-2pi i/8} twiddles; !FWD: conjugate
// ---------------------------------------------------------------------------
template <bool FWD>
__device__ __forceinline__ void dft8(float2 v[8]) {
    const float C = 0.70710678118654752440f;
    float2 s0 = cadd(v[0], v[4]), d0 = csub(v[0], v[4]);
    float2 s1 = cadd(v[1], v[5]), d1 = csub(v[1], v[5]);
    float2 s2 = cadd(v[2], v[6]), d2 = csub(v[2], v[6]);
    float2 s3 = cadd(v[3], v[7]), d3 = csub(v[3], v[7]);
    float2 E0 = cadd(s0, s2), E2 = csub(s0, s2);
    float2 jd2 = FWD ? make_float2(d2.y, -d2.x) : make_float2(-d2.y, d2.x);
    float2 E1 = cadd(d0, jd2);
    float2 E3 = csub(d0, jd2);
    float2 O0 = cadd(s1, s3), O2 = csub(s1, s3);
    float2 jd3 = FWD ? make_float2(d3.y, -d3.x) : make_float2(-d3.y, d3.x);
    float2 O1 = cadd(d1, jd3), O3 = csub(d1, jd3);
    float2 tO1 = FWD ? make_float2(C * (O1.x + O1.y), C * (O1.y - O1.x))
                     : make_float2(C * (O1.x - O1.y), C * (O1.y + O1.x));
    float2 tO2 = FWD ? make_float2(O2.y, -O2.x) : make_float2(-O2.y, O2.x);
    float2 tO3 = FWD ? make_float2(C * (O3.y - O3.x), -C * (O3.x + O3.y))
                     : make_float2(-C * (O3.x + O3.y), C * (O3.x - O3.y));
    v[0] = cadd(E0, O0);  v[4] = csub(E0, O0);
    v[1] = cadd(E1, tO1); v[5] = csub(E1, tO1);
    v[2] = cadd(E2, tO2); v[6] = csub(E2, tO2);
    v[3] = cadd(E3, tO3); v[7] = csub(E3, tO3);
}

// ---------------------------------------------------------------------------
// Twiddle table init
// ---------------------------------------------------------------------------
__global__ void twiddle_kernel() {
    const int t = blockIdx.x * blockDim.x + threadIdx.x;
    const float TWO_PI = 6.2831853071795864769f;
    if (t < 512) {
        float s, c;
        sincosf(-TWO_PI * (float)t / (float)NFFT, &s, &c);
        g_W1[t] = make_float2(c, s);
    }
    if (t < 64) {
        float s, c;
        sincosf(-TWO_PI * (float)(8 * t) / (float)NFFT, &s, &c);
        g_W2[t] = make_float2(c, s);
    }
    if (t < 8) {
        float s, c;
        sincosf(-TWO_PI * (float)(64 * t) / (float)NFFT, &s, &c);
        g_W3[t] = make_float2(c, s);
    }
}

// ===========================================================================
// Register-resident radix-8 4096-pt FFT, 512 threads, 8 points/thread.
// Thread coords: t = m*64 + m'*8 + n3 ; n2 = t&63.
// Exchanges use XOR swizzles -> all LDS/STS phases conflict-free.
// ===========================================================================

#define FFT8_FWD_BODY(S, t, m, mp, n3, n2, v)                                   \
    {                                                                           \
        dft8<true>(v);                                                          \
        TWIDDLE_FWD(v, g_W1[t]);                                                \
        _Pragma("unroll") for (int j = 0; j < 8; j++)                           \
            S[(j << 9) + t] = v[j];                                             \
        __syncthreads();                                                        \
        _Pragma("unroll") for (int r = 0; r < 8; r++)                           \
            v[r] = S[(m << 9) + n2 + (r << 6)];                                 \
        __syncthreads();                                                        \
        dft8<true>(v);                                                          \
        TWIDDLE_FWD(v, g_W2[n2]);                                               \
        _Pragma("unroll") for (int j = 0; j < 8; j++)                           \
            S[(m << 9) + (j << 6) + (n2 ^ (j << 3))] = v[j];                    \
        __syncthreads();                                                        \
        _Pragma("unroll") for (int r = 0; r < 8; r++)                           \
            v[r] = S[(m << 9) + (mp << 6) + ((r ^ mp) << 3) + n3];              \
        __syncthreads();                                                        \
        dft8<true>(v);                                                          \
        TWIDDLE_FWD(v, g_W3[n3]);                                               \
        _Pragma("unroll") for (int j = 0; j < 8; j++)                           \
            S[(n3 << 9) + (t & 504) + (j ^ n3)] = v[j];                         \
        __syncthreads();                                                        \
        _Pragma("unroll") for (int j = 0; j < 8; j++)                           \
            v[j] = S[(j << 9) + (t & 504) + ((t & 7) ^ j)];                     \
        dft8<true>(v);                                                          \
    }

#define FFT8_INV_BODY(S, t, m, mp, n3, n2, v)                                   \
    {                                                                           \
        dft8<false>(v);                                                         \
        /* writes hit exactly this thread's own stage-D read addrs: race-free */\
        _Pragma("unroll") for (int j = 0; j < 8; j++)                           \
            S[(j << 9) + (t & 504) + ((t & 7) ^ j)] = v[j];                     \
        __syncthreads();                                                        \
        _Pragma("unroll") for (int j = 0; j < 8; j++)                           \
            v[j] = S[(n3 << 9) + (t & 504) + (j ^ n3)];                         \
        __syncthreads();                                                        \
        TWIDDLE_INV(v, g_W3[n3]);                                               \
        dft8<false>(v);                                                         \
        _Pragma("unroll") for (int r = 0; r < 8; r++)                           \
            S[(m << 9) + (mp << 6) + ((r ^ mp) << 3) + n3] = v[r];              \
        __syncthreads();                                                        \
        _Pragma("unroll") for (int j = 0; j < 8; j++)                           \
            v[j] = S[(m << 9) + (j << 6) + (n2 ^ (j << 3))];                    \
        __syncthreads();                                                        \
        TWIDDLE_INV(v, g_W2[n2]);                                               \
        dft8<false>(v);                                                         \
        _Pragma("unroll") for (int r = 0; r < 8; r++)                           \
            S[(m << 9) + n2 + (r << 6)] = v[r];                                 \
        __syncthreads();                                                        \
        _Pragma("unroll") for (int j = 0; j < 8; j++)                           \
            v[j] = S[(j << 9) + t];                                             \
        TWIDDLE_INV(v, g_W1[t]);                                                \
        dft8<false>(v);                                                         \
    }

// ===========================================================================
// Fused prep kernel: AR-coefficient setup + warp-shuffle Q build + blocked
// scan + filter taps straight into FFT registers + forward FFT -> g_Fs.
// grid = H blocks, 512 threads.
// ===========================================================================
struct PrepSmemP {
    float Q[NST * QPITCH];   // block-step matrix rows
    float A[ASZ];            // a_{-63..2048}
    float tmp[NST];
    float dd[NST];
    float c[NST];
    float e[NST];
};
union PrepSmem {
    PrepSmemP p;
    float2 S[NFFT];          // FFT workspace (reuses Q/A after taps are in regs)
};

__global__ __launch_bounds__(512, 2) void prep_kernel(const float* __restrict__ k) {
    __shared__ PrepSmem sm;
    const int h   = blockIdx.x;
    const int tid = threadIdx.x;

    // zero the a-array (left pad + body)
    for (int i = tid; i < ASZ; i += 512) sm.p.A[i] = 0.0f;

    float kr = 0.0f, kn = 0.0f, ddv = 0.0f;
    if (tid < NST) {
        kr = k[h * NST + tid];
        sm.p.tmp[tid] = fminf(fmaxf(kr, 1.0f / 16.0f), 1.0f);
    }
    __syncthreads();
    if (tid < NST) {
        float ssum = 0.0f;
#pragma unroll
        for (int i = 0; i < NST; i++) ssum += sm.p.tmp[i];
        kn  = sm.p.tmp[tid] / ssum;
        ddv = 1.0f / (1.0f + kn);
        sm.p.dd[tid] = ddv;
    }
    __syncthreads();
    if (tid < NST) {
        float D = 1.0f;
        for (int m = 0; m < tid; m++) D *= sm.p.dd[m];
        const float w = (tid < NST - 1) ? kn * ddv : 1.0f;
        sm.p.c[tid] = w * D;
        sm.p.e[tid] = kr * D;
        if (tid == 0) sm.p.A[NST - 1] = 1.0f;  // a_0 = 1
    }
    __syncthreads();

    // --- Q build, warp 0 only, register+shuffle recurrence:
    //     Q[r][j] = Q[r-1][0]*c[j] + Q[r-1][j+1]   (Q[r-1][64] = 0)
    if (tid < 32) {
        const int lane = tid;
        const float cA = sm.p.c[lane];
        const float cB = sm.p.c[lane + 32];
        float qA = cA, qB = cB;                 // row 0 = c
        sm.p.Q[lane] = qA;
        sm.p.Q[lane + 32] = qB;
        for (int r = 1; r < NST; r++) {
            const float q0  = __shfl_sync(0xffffffffu, qA, 0);
            const float qB0 = __shfl_sync(0xffffffffu, qB, 0);
            float nA = __shfl_down_sync(0xffffffffu, qA, 1);
            float nB = __shfl_down_sync(0xffffffffu, qB, 1);
            if (lane == 31) { nA = qB0; nB = 0.0f; }
            qA = fmaf(q0, cA, nA);
            qB = fmaf(q0, cB, nB);
            sm.p.Q[r * QPITCH + lane] = qA;
            sm.p.Q[r * QPITCH + lane + 32] = qB;
        }
    }
    __syncthreads();

    // --- Blocked AR scan: threads 0..63, named barrier (others park below)
    if (tid < NST) {
        const int j = tid;
        const float* Qr = &sm.p.Q[j * QPITCH];
        for (int t = 0; t < LL; t += NST) {
            const float* Ab = &sm.p.A[NST - 1 + t];
            float s0 = 0.0f, s1 = 0.0f, s2 = 0.0f, s3 = 0.0f;
#pragma unroll
            for (int m = 0; m < NST; m += 4) {
                s0 += Qr[m]     * Ab[-m];
                s1 += Qr[m + 1] * Ab[-m - 1];
                s2 += Qr[m + 2] * Ab[-m - 2];
                s3 += Qr[m + 3] * Ab[-m - 3];
            }
            sm.p.A[NST + t + j] = (s0 + s1) + (s2 + s3);  // disjoint from reads
            asm volatile("bar.sync 1, 64;" ::: "memory");
        }
    }
    __syncthreads();

    // --- Filter taps straight into FFT input registers:
    //     v[r].x = f[tid + 512 r] = sum_n e[n] * a_{i-n},  r = 0..3
    const int t = tid;
    float a0 = 0.0f, a1 = 0.0f, a2 = 0.0f, a3 = 0.0f;
    {
        const float* Ab = &sm.p.A[NST - 1 + t];
#pragma unroll
        for (int n = 0; n < NST; n++) {
            const float en = sm.p.e[n];
            a0 += en * Ab[-n];
            a1 += en * Ab[512 - n];
            a2 += en * Ab[1024 - n];
            a3 += en * Ab[1536 - n];
        }
    }
    float2 v[8];
    v[0] = make_float2(a0, 0.0f);
    v[1] = make_float2(a1, 0.0f);
    v[2] = make_float2(a2, 0.0f);
    v[3] = make_float2(a3, 0.0f);
#pragma unroll
    for (int r = 4; r < 8; r++) v[r] = make_float2(0.0f, 0.0f);
    __syncthreads();   // taps are in registers; safe to reuse smem as S

    // --- Forward FFT (same machinery/order as conv)
    float2* S = sm.S;
    const int m = t >> 6, mp = (t >> 3) & 7, n3 = t & 7, n2 = t & 63;
    FFT8_FWD_BODY(S, t, m, mp, n3, n2, v);

    const float sc = 1.0f / (float)NFFT;
    float2* out = g_Fs + (size_t)h * NFFT + 8 * t;
#pragma unroll
    for (int j = 0; j < 8; j++)
        out[j] = make_float2(v[j].x * sc, v[j].y * sc);
}

// ---------------------------------------------------------------------------
// Conv kernel: causal FFT convolution, TWO batch rows per CTA (real filter =>
// conv(u0 + i*u1, f) = y0 + i*y1 exactly). grid = (B/2)*H = 4096, 512 thr.
// ---------------------------------------------------------------------------
__global__ __launch_bounds__(512, 2) void conv_kernel(const float* __restrict__ u,
                                                      float* __restrict__ y) {
    __shared__ float2 S[NFFT];
    const int t = threadIdx.x;
    const int m = t >> 6, mp = (t >> 3) & 7, n3 = t & 7, n2 = t & 63;
    const int h = blockIdx.x & (HH - 1);
    const int p = blockIdx.x >> 9;  // 0..7

    const float* u0 = u + ((size_t)p * HH + h) * LL;
    const float* u1 = u + ((size_t)(p + BB / 2) * HH + h) * LL;

    float2 v[8];
#pragma unroll
    for (int r = 0; r < 8; r++)
        v[r] = (r < 4) ? make_float2(u0[t + 512 * r], u1[t + 512 * r])
                       : make_float2(0.0f, 0.0f);

    FFT8_FWD_BODY(S, t, m, mp, n3, n2, v);

    // pointwise multiply in registers (coalesced float4 spectrum reads)
    const float4* F4 = reinterpret_cast<const float4*>(g_Fs + (size_t)h * NFFT) + 4 * t;
#pragma unroll
    for (int jj = 0; jj < 4; jj++) {
        const float4 f = __ldg(&F4[jj]);
        v[2 * jj]     = cmul(v[2 * jj],     make_float2(f.x, f.y));
        v[2 * jj + 1] = cmul(v[2 * jj + 1], make_float2(f.z, f.w));
    }

    FFT8_INV_BODY(S, t, m, mp, n3, n2, v);

    float* y0 = y + ((size_t)p * HH + h) * LL;
    float* y1 = y + ((size_t)(p + BB / 2) * HH + h) * LL;
#pragma unroll
    for (int r = 0; r < 4; r++) {
        y0[t + 512 * r] = v[r].x;
        y1[t + 512 * r] = v[r].y;
    }
}

// ---------------------------------------------------------------------------
extern "C" void kernel_launch(void* const* d_in, const int* in_sizes, int n_in,
                              void* d_out, int out_size) {
    const float* u;
    const float* k;
    if (in_sizes[0] == BB * HH * LL) {
        u = (const float*)d_in[0];
        k = (const float*)d_in[1];
    } else {
        u = (const float*)d_in[1];
        k = (const float*)d_in[0];
    }
    float* y = (float*)d_out;

    twiddle_kernel<<<2, 256>>>();
    prep_kernel<<<HH, 512>>>(k);
    conv_kernel<<<(BB / 2) * HH, 512>>>(u, y);
}